// round 12
// baseline (speedup 1.0000x reference)
#include <cuda_runtime.h>
#include <cuda_bf16.h>

// ---------------------------------------------------------------------------
// RGCN layer, 3 launches + 1 memset:
//  k_pre  : basis expansion (ILP=4) | node hs + (ht,sl) float2 (A_w smem-staged)
//           | relation histogram + last-block scan
//  k_scat : counting-sort scatter (int4 {src,tgt,eid}) | zero out
//  k_main : per-relation blocks; fused attention + message + self-loop;
//           rel_w + are/atr in smem, edge prefetch, ILP=4, full-warp red.v4
// ---------------------------------------------------------------------------

#define RMAX 256
#define NMAX 16384
#define EMAX 262144

typedef unsigned long long u64;

__device__ __forceinline__ u64 pk2(float lo, float hi) {
    u64 r; asm("mov.b64 %0, {%1, %2};" : "=l"(r) : "f"(lo), "f"(hi)); return r;
}
__device__ __forceinline__ void fma2(u64& d, u64 a, u64 b) {
    asm("fma.rn.f32x2 %0, %1, %2, %0;" : "+l"(d) : "l"(a), "l"(b));
}
__device__ __forceinline__ float upk_sum(u64 v) {
    float lo, hi; asm("mov.b64 {%0, %1}, %2;" : "=f"(lo), "=f"(hi) : "l"(v));
    return lo + hi;
}

__device__ float  g_relw[RMAX * 1024];
__device__ float  g_hs[NMAX * 32];
__device__ float2 g_htsl[NMAX * 32];   // interleaved (ht, sl) per node/lane
__device__ int4   g_edge[EMAX];        // sorted {src, tgt, eid, 0}
__device__ int    g_off[RMAX + 1];
__device__ int    g_cur[RMAX];
struct Counters { int cnt[RMAX]; int done; };
__device__ Counters g_c;

// ---- launch 1: basis | node hs/(ht,sl) | rel histogram + scan ------------------
__global__ void __launch_bounds__(256)
k_pre(const float* __restrict__ weight,    // [NB,32,32]
      const float* __restrict__ w_comp,    // [R,NB]
      const float* __restrict__ node_feat, // [N,32]
      const float* __restrict__ A_w,       // [32,128]
      const float* __restrict__ A_b,       // [32]
      const float* __restrict__ slw,       // [32,32]
      const int*   __restrict__ rels,      // [E]
      int NB, int R, int N, int E, int nbNode, int nbHist)
{
    int b = blockIdx.x;
    const int tid = threadIdx.x;

    if (b < R) {                                    // --- basis expansion, ILP=4 ---
        const float* wc = w_comp + b * NB;
        float acc0 = 0.f, acc1 = 0.f, acc2 = 0.f, acc3 = 0.f;
        for (int k = 0; k < NB; ++k) {
            const float wcb = __ldg(wc + k);
            const float* wp = weight + k * 1024 + tid;
            acc0 = fmaf(wcb, __ldg(wp +   0), acc0);
            acc1 = fmaf(wcb, __ldg(wp + 256), acc1);
            acc2 = fmaf(wcb, __ldg(wp + 512), acc2);
            acc3 = fmaf(wcb, __ldg(wp + 768), acc3);
        }
        g_relw[b * 1024 + tid +   0] = acc0;
        g_relw[b * 1024 + tid + 256] = acc1;
        g_relw[b * 1024 + tid + 512] = acc2;
        g_relw[b * 1024 + tid + 768] = acc3;
        return;
    }
    b -= R;

    if (b < nbNode) {                               // --- node hs / (ht,sl) ---
        __shared__ float sA[32 * 129];
        for (int idx = tid; idx < 4096; idx += 256)
            sA[(idx >> 7) * 129 + (idx & 127)] = __ldg(A_w + idx);
        __syncthreads();

        const int lane = tid & 31;
        const int warp = tid >> 5;
        float aws[32], awt[32], slc[32];
#pragma unroll
        for (int i = 0; i < 32; ++i) {
            aws[i] = sA[lane * 129 + i];
            awt[i] = sA[lane * 129 + 32 + i];
            slc[i] = __ldg(slw + i * 32 + lane);    // coalesced
        }
        const float ab = __ldg(A_b + lane);
        // 64 nodes per block, 8 per warp
#pragma unroll
        for (int k = 0; k < 8; ++k) {
            const int n = b * 64 + warp * 8 + k;
            if (n < N) {
                const float4* fp = (const float4*)(node_feat + (size_t)n * 32);
                float hs = ab, ht = 0.f, sl = 0.f;
#pragma unroll
                for (int c = 0; c < 8; ++c) {
                    float4 f = __ldg(fp + c);
                    hs = fmaf(f.x, aws[4*c+0], hs); ht = fmaf(f.x, awt[4*c+0], ht); sl = fmaf(f.x, slc[4*c+0], sl);
                    hs = fmaf(f.y, aws[4*c+1], hs); ht = fmaf(f.y, awt[4*c+1], ht); sl = fmaf(f.y, slc[4*c+1], sl);
                    hs = fmaf(f.z, aws[4*c+2], hs); ht = fmaf(f.z, awt[4*c+2], ht); sl = fmaf(f.z, slc[4*c+2], sl);
                    hs = fmaf(f.w, aws[4*c+3], hs); ht = fmaf(f.w, awt[4*c+3], ht); sl = fmaf(f.w, slc[4*c+3], sl);
                }
                g_hs[(size_t)n * 32 + lane]   = hs;
                g_htsl[(size_t)n * 32 + lane] = make_float2(ht, sl);
            }
        }
        return;
    }
    b -= nbNode;

    // --- relation histogram (2048 edges/block) + last-block scan ---
    __shared__ int sh[RMAX];
    for (int i = tid; i < RMAX; i += 256) sh[i] = 0;
    __syncthreads();
    const int base = b * 2048;
#pragma unroll
    for (int k = 0; k < 8; ++k) {
        const int e = base + k * 256 + tid;
        if (e < E) atomicAdd(&sh[__ldg(rels + e)], 1);
    }
    __syncthreads();
    for (int i = tid; i < RMAX; i += 256) {
        const int v = sh[i];
        if (v) atomicAdd(&g_c.cnt[i], v);
    }
    __threadfence();
    __syncthreads();
    __shared__ int s_last;
    if (tid == 0)
        s_last = (atomicAdd(&g_c.done, 1) == nbHist - 1);
    __syncthreads();
    if (s_last) {                                   // --- last block: scan ---
        __shared__ int buf[RMAX];
        const int c = atomicAdd(&g_c.cnt[tid], 0);  // coherent read
        buf[tid] = c;
        __syncthreads();
#pragma unroll
        for (int d = 1; d < RMAX; d <<= 1) {
            const int v = (tid >= d) ? buf[tid - d] : 0;
            __syncthreads();
            buf[tid] += v;
            __syncthreads();
        }
        if (tid == 0) g_off[0] = 0;
        g_off[tid + 1] = buf[tid];
        g_cur[tid]     = buf[tid] - c;              // exclusive
    }
}

// ---- launch 2: counting-sort scatter | zero out ----------------------------------
__global__ void __launch_bounds__(256)
k_scat(const int* __restrict__ edges,  // [2,E]
       const int* __restrict__ rels,   // [E]
       float*     __restrict__ out,
       int E, int nbHist, int out_sz)
{
    int b = blockIdx.x;
    const int tid = threadIdx.x;

    if (b >= nbHist) {                              // --- zero out blocks ---
        b -= nbHist;
        const int i0 = (b * 256 + tid) * 4;
        if (i0 + 3 < out_sz)
            *(float4*)(out + i0) = make_float4(0.f, 0.f, 0.f, 0.f);
        else
            for (int i = i0; i < out_sz; ++i) out[i] = 0.f;
        return;
    }

    __shared__ int h[RMAX];
    __shared__ int cur[RMAX];
    for (int i = tid; i < RMAX; i += 256) h[i] = 0;
    __syncthreads();
    const int base = b * 2048;
    int rr[8];
#pragma unroll
    for (int k = 0; k < 8; ++k) {
        const int e = base + k * 256 + tid;
        rr[k] = (e < E) ? __ldg(rels + e) : -1;
        if (rr[k] >= 0) atomicAdd(&h[rr[k]], 1);
    }
    __syncthreads();
    for (int i = tid; i < RMAX; i += 256) {
        const int v = h[i];
        cur[i] = v ? atomicAdd(&g_cur[i], v) : 0;
    }
    __syncthreads();
#pragma unroll
    for (int k = 0; k < 8; ++k) {
        if (rr[k] >= 0) {
            const int e   = base + k * 256 + tid;
            const int pos = atomicAdd(&cur[rr[k]], 1);
            g_edge[pos] = make_int4(__ldg(edges + e), __ldg(edges + E + e), e, 0);
        }
    }
}

// ---- launch 3: fused attention + message + self-loop, red.v4, ILP = 4 -----------
__global__ void __launch_bounds__(256)
k_main(const float* __restrict__ node_feat,
       const float* __restrict__ ttr,   // [E,32]
       const float* __restrict__ tre,   // [E,32]
       const float* __restrict__ A_w,   // [32,128]
       const float* __restrict__ B_w,   // [32]
       const float* __restrict__ B_b,   // [1]
       float*       __restrict__ out)
{
    const int r     = blockIdx.x;
    const int start = __ldg(&g_off[r]);
    const int end   = __ldg(&g_off[r + 1]);
    if (start >= end) return;            // block-uniform

    const int tid  = threadIdx.x;
    const int lane = tid & 31;

    // are/atr coefficients packed as f32x2 in smem: row = output lane
    __shared__ u64 sAre[32 * 17];
    __shared__ u64 sAtr[32 * 17];
    __shared__ u64 sRw [16 * 32];         // rel_w[r] packed: [i][lane]
    for (int idx = tid; idx < 32 * 16; idx += 256) {
        const int row = idx >> 4, i = idx & 15;
        sAre[row * 17 + i] = pk2(__ldg(A_w + row * 128 + 64 + 2*i),
                                 __ldg(A_w + row * 128 + 64 + 2*i + 1));
        sAtr[row * 17 + i] = pk2(__ldg(A_w + row * 128 + 96 + 2*i),
                                 __ldg(A_w + row * 128 + 96 + 2*i + 1));
    }
    for (int idx = tid; idx < 512; idx += 256) {
        const int i = idx >> 5, ln = idx & 31;
        sRw[i * 32 + ln] = pk2(__ldg(&g_relw[r * 1024 + i * 64 + ln]),
                               __ldg(&g_relw[r * 1024 + i * 64 + 32 + ln]));
    }
    __syncthreads();

    const float bw = __ldg(B_w + lane);
    const float bb = __ldg(B_b);

    const int w = blockIdx.y * 8 + (tid >> 5);
    const int W = gridDim.y * 8;

    int i0 = start + w * 4;
    if (i0 >= end) return;

    int4 e4[4];                                     // prefetched edge records
#pragma unroll
    for (int k = 0; k < 4; ++k)
        e4[k] = __ldg(&g_edge[min(i0 + k, end - 1)]);

    while (i0 < end) {
        int ss[4], tt[4], ee[4];
#pragma unroll
        for (int k = 0; k < 4; ++k) {
            ss[k] = e4[k].x; tt[k] = e4[k].y; ee[k] = e4[k].z;
        }
        float hh[4], sl[4];
#pragma unroll
        for (int k = 0; k < 4; ++k) {
            const float2 hts = __ldg(&g_htsl[(size_t)tt[k] * 32 + lane]);
            hh[k] = __ldg(&g_hs[(size_t)ss[k] * 32 + lane]) + hts.x;
            sl[k] = hts.y;
        }

        // prefetch next iteration's edge records (hidden behind compute)
        const int i1 = i0 + W * 4;
        if (i1 < end) {
#pragma unroll
            for (int k = 0; k < 4; ++k)
                e4[k] = __ldg(&g_edge[min(i1 + k, end - 1)]);
        }

        u64 aacc[4] = {0ull, 0ull, 0ull, 0ull};
        u64 macc[4] = {0ull, 0ull, 0ull, 0ull};
#pragma unroll
        for (int c = 0; c < 8; ++c) {
            const u64 a0 = sAre[lane * 17 + 2*c];
            const u64 a1 = sAre[lane * 17 + 2*c + 1];
            const u64 t0 = sAtr[lane * 17 + 2*c];
            const u64 t1 = sAtr[lane * 17 + 2*c + 1];
            const u64 r0 = sRw[(2*c)     * 32 + lane];
            const u64 r1 = sRw[(2*c + 1) * 32 + lane];
#pragma unroll
            for (int k = 0; k < 4; ++k) {
                ulonglong2 X = __ldg((const ulonglong2*)(tre + (size_t)ee[k] * 32) + c);
                ulonglong2 Y = __ldg((const ulonglong2*)(ttr + (size_t)ee[k] * 32) + c);
                ulonglong2 F = __ldg((const ulonglong2*)(node_feat + (size_t)ss[k] * 32) + c);
                fma2(aacc[k], X.x, a0);  fma2(aacc[k], X.y, a1);
                fma2(aacc[k], Y.x, t0);  fma2(aacc[k], Y.y, t1);
                fma2(macc[k], F.x, r0);
                fma2(macc[k], F.y, r1);
            }
        }
        float p[4];
#pragma unroll
        for (int k = 0; k < 4; ++k)
            p[k] = fmaxf(hh[k] + upk_sum(aacc[k]), 0.f) * bw;
#pragma unroll
        for (int o = 16; o; o >>= 1) {
#pragma unroll
            for (int k = 0; k < 4; ++k)
                p[k] += __shfl_xor_sync(0xffffffffu, p[k], o);
        }
        float v[4];
#pragma unroll
        for (int k = 0; k < 4; ++k) {
            const float att = 1.f / (1.f + __expf(-(p[k] + bb)));
            v[k] = fmaf(upk_sum(macc[k]), att, sl[k]);
        }

        // all 32 lanes issue one red.v4: lane group k = edge k, 8 lanes each
        const int kk = lane >> 3;           // which edge this lane stores
        const int g0 = (lane & 7) * 4;      // feature offset
        float q0 = 0.f, q1 = 0.f, q2 = 0.f, q3 = 0.f;
#pragma unroll
        for (int k = 0; k < 4; ++k) {
            float a  = __shfl_sync(0xffffffffu, v[k], g0 + 0);
            float bq = __shfl_sync(0xffffffffu, v[k], g0 + 1);
            float cq = __shfl_sync(0xffffffffu, v[k], g0 + 2);
            float dq = __shfl_sync(0xffffffffu, v[k], g0 + 3);
            if (kk == k) { q0 = a; q1 = bq; q2 = cq; q3 = dq; }
        }
        if (i0 + kk < end) {
            float* p_ = out + (size_t)tt[kk] * 32 + g0;
            asm volatile("red.global.add.v4.f32 [%0], {%1, %2, %3, %4};"
                         :: "l"(p_), "f"(q0), "f"(q1), "f"(q2), "f"(q3) : "memory");
        }
        i0 = i1;
    }
}

extern "C" void kernel_launch(void* const* d_in, const int* in_sizes, int n_in,
                              void* d_out, int out_size)
{
    const float* node_feat = (const float*)d_in[0];
    const float* ttr       = (const float*)d_in[1];
    const float* tre       = (const float*)d_in[2];
    const float* weight    = (const float*)d_in[3];
    const float* w_comp    = (const float*)d_in[4];
    const float* slw       = (const float*)d_in[5];
    const float* A_w       = (const float*)d_in[6];
    const float* A_b       = (const float*)d_in[7];
    const float* B_w       = (const float*)d_in[8];
    const float* B_b       = (const float*)d_in[9];
    const int*   edges     = (const int*)d_in[10];
    const int*   rels      = (const int*)d_in[11];
    float* out = (float*)d_out;

    const int E  = in_sizes[11];
    const int N  = in_sizes[0] / 32;
    const int NB = in_sizes[3] / 1024;
    const int R  = in_sizes[4] / NB;

    const int nbNode = (N + 63) / 64;
    const int nbHist = (E + 2047) / 2048;
    const int nbZero = (out_size + 1023) / 1024;   // 256 thr * 4 floats

    void* cptr = nullptr;
    cudaGetSymbolAddress(&cptr, g_c);
    cudaMemsetAsync(cptr, 0, sizeof(Counters));

    k_pre<<<R + nbNode + nbHist, 256>>>(weight, w_comp, node_feat, A_w, A_b,
                                        slw, rels, NB, R, N, E, nbNode, nbHist);
    k_scat<<<nbHist + nbZero, 256>>>(edges, rels, out, E, nbHist, out_size);
    k_main<<<dim3(R, 10), 256>>>(node_feat, ttr, tre, A_w, B_w, B_b, out);
}

// round 13
// speedup vs baseline: 1.0111x; 1.0111x over previous
#include <cuda_runtime.h>
#include <cuda_bf16.h>

// ---------------------------------------------------------------------------
// RGCN layer, 3 launches + 1 memset:
//  k_pre  : basis expansion (ILP=4) | node hs + (ht,sl) float2 (A_w smem-staged)
//           | relation histogram + last-block scan
//  k_scat : counting-sort scatter (int4 {src,tgt,eid}) | zero out
//  k_main : per-relation blocks; fused attn+msg+self-loop in TWO PHASES
//           (low reg pressure, 3 blocks/SM); weights in smem; full-warp red.v4
// ---------------------------------------------------------------------------

#define RMAX 256
#define NMAX 16384
#define EMAX 262144

typedef unsigned long long u64;

__device__ __forceinline__ u64 pk2(float lo, float hi) {
    u64 r; asm("mov.b64 %0, {%1, %2};" : "=l"(r) : "f"(lo), "f"(hi)); return r;
}
__device__ __forceinline__ void fma2(u64& d, u64 a, u64 b) {
    asm("fma.rn.f32x2 %0, %1, %2, %0;" : "+l"(d) : "l"(a), "l"(b));
}
__device__ __forceinline__ float upk_sum(u64 v) {
    float lo, hi; asm("mov.b64 {%0, %1}, %2;" : "=f"(lo), "=f"(hi) : "l"(v));
    return lo + hi;
}

__device__ float  g_relw[RMAX * 1024];
__device__ float  g_hs[NMAX * 32];
__device__ float2 g_htsl[NMAX * 32];   // interleaved (ht, sl) per node/lane
__device__ int4   g_edge[EMAX];        // sorted {src, tgt, eid, 0}
__device__ int    g_off[RMAX + 1];
__device__ int    g_cur[RMAX];
struct Counters { int cnt[RMAX]; int done; };
__device__ Counters g_c;

// ---- launch 1: basis | node hs/(ht,sl) | rel histogram + scan ------------------
__global__ void __launch_bounds__(256)
k_pre(const float* __restrict__ weight,    // [NB,32,32]
      const float* __restrict__ w_comp,    // [R,NB]
      const float* __restrict__ node_feat, // [N,32]
      const float* __restrict__ A_w,       // [32,128]
      const float* __restrict__ A_b,       // [32]
      const float* __restrict__ slw,       // [32,32]
      const int*   __restrict__ rels,      // [E]
      int NB, int R, int N, int E, int nbNode, int nbHist)
{
    int b = blockIdx.x;
    const int tid = threadIdx.x;

    if (b < R) {                                    // --- basis expansion, ILP=4 ---
        const float* wc = w_comp + b * NB;
        float acc0 = 0.f, acc1 = 0.f, acc2 = 0.f, acc3 = 0.f;
        for (int k = 0; k < NB; ++k) {
            const float wcb = __ldg(wc + k);
            const float* wp = weight + k * 1024 + tid;
            acc0 = fmaf(wcb, __ldg(wp +   0), acc0);
            acc1 = fmaf(wcb, __ldg(wp + 256), acc1);
            acc2 = fmaf(wcb, __ldg(wp + 512), acc2);
            acc3 = fmaf(wcb, __ldg(wp + 768), acc3);
        }
        g_relw[b * 1024 + tid +   0] = acc0;
        g_relw[b * 1024 + tid + 256] = acc1;
        g_relw[b * 1024 + tid + 512] = acc2;
        g_relw[b * 1024 + tid + 768] = acc3;
        return;
    }
    b -= R;

    if (b < nbNode) {                               // --- node hs / (ht,sl) ---
        __shared__ float sA[32 * 129];
        for (int idx = tid; idx < 4096; idx += 256)
            sA[(idx >> 7) * 129 + (idx & 127)] = __ldg(A_w + idx);
        __syncthreads();

        const int lane = tid & 31;
        const int warp = tid >> 5;
        float aws[32], awt[32], slc[32];
#pragma unroll
        for (int i = 0; i < 32; ++i) {
            aws[i] = sA[lane * 129 + i];
            awt[i] = sA[lane * 129 + 32 + i];
            slc[i] = __ldg(slw + i * 32 + lane);    // coalesced
        }
        const float ab = __ldg(A_b + lane);
        // 64 nodes per block, 8 per warp
#pragma unroll
        for (int k = 0; k < 8; ++k) {
            const int n = b * 64 + warp * 8 + k;
            if (n < N) {
                const float4* fp = (const float4*)(node_feat + (size_t)n * 32);
                float hs = ab, ht = 0.f, sl = 0.f;
#pragma unroll
                for (int c = 0; c < 8; ++c) {
                    float4 f = __ldg(fp + c);
                    hs = fmaf(f.x, aws[4*c+0], hs); ht = fmaf(f.x, awt[4*c+0], ht); sl = fmaf(f.x, slc[4*c+0], sl);
                    hs = fmaf(f.y, aws[4*c+1], hs); ht = fmaf(f.y, awt[4*c+1], ht); sl = fmaf(f.y, slc[4*c+1], sl);
                    hs = fmaf(f.z, aws[4*c+2], hs); ht = fmaf(f.z, awt[4*c+2], ht); sl = fmaf(f.z, slc[4*c+2], sl);
                    hs = fmaf(f.w, aws[4*c+3], hs); ht = fmaf(f.w, awt[4*c+3], ht); sl = fmaf(f.w, slc[4*c+3], sl);
                }
                g_hs[(size_t)n * 32 + lane]   = hs;
                g_htsl[(size_t)n * 32 + lane] = make_float2(ht, sl);
            }
        }
        return;
    }
    b -= nbNode;

    // --- relation histogram (2048 edges/block) + last-block scan ---
    __shared__ int sh[RMAX];
    for (int i = tid; i < RMAX; i += 256) sh[i] = 0;
    __syncthreads();
    const int base = b * 2048;
#pragma unroll
    for (int k = 0; k < 8; ++k) {
        const int e = base + k * 256 + tid;
        if (e < E) atomicAdd(&sh[__ldg(rels + e)], 1);
    }
    __syncthreads();
    for (int i = tid; i < RMAX; i += 256) {
        const int v = sh[i];
        if (v) atomicAdd(&g_c.cnt[i], v);
    }
    __threadfence();
    __syncthreads();
    __shared__ int s_last;
    if (tid == 0)
        s_last = (atomicAdd(&g_c.done, 1) == nbHist - 1);
    __syncthreads();
    if (s_last) {                                   // --- last block: scan ---
        __shared__ int buf[RMAX];
        const int c = atomicAdd(&g_c.cnt[tid], 0);  // coherent read
        buf[tid] = c;
        __syncthreads();
#pragma unroll
        for (int d = 1; d < RMAX; d <<= 1) {
            const int v = (tid >= d) ? buf[tid - d] : 0;
            __syncthreads();
            buf[tid] += v;
            __syncthreads();
        }
        if (tid == 0) g_off[0] = 0;
        g_off[tid + 1] = buf[tid];
        g_cur[tid]     = buf[tid] - c;              // exclusive
    }
}

// ---- launch 2: counting-sort scatter | zero out ----------------------------------
__global__ void __launch_bounds__(256)
k_scat(const int* __restrict__ edges,  // [2,E]
       const int* __restrict__ rels,   // [E]
       float*     __restrict__ out,
       int E, int nbHist, int out_sz)
{
    int b = blockIdx.x;
    const int tid = threadIdx.x;

    if (b >= nbHist) {                              // --- zero out blocks ---
        b -= nbHist;
        const int i0 = (b * 256 + tid) * 4;
        if (i0 + 3 < out_sz)
            *(float4*)(out + i0) = make_float4(0.f, 0.f, 0.f, 0.f);
        else
            for (int i = i0; i < out_sz; ++i) out[i] = 0.f;
        return;
    }

    __shared__ int h[RMAX];
    __shared__ int cur[RMAX];
    for (int i = tid; i < RMAX; i += 256) h[i] = 0;
    __syncthreads();
    const int base = b * 2048;
    int rr[8];
#pragma unroll
    for (int k = 0; k < 8; ++k) {
        const int e = base + k * 256 + tid;
        rr[k] = (e < E) ? __ldg(rels + e) : -1;
        if (rr[k] >= 0) atomicAdd(&h[rr[k]], 1);
    }
    __syncthreads();
    for (int i = tid; i < RMAX; i += 256) {
        const int v = h[i];
        cur[i] = v ? atomicAdd(&g_cur[i], v) : 0;
    }
    __syncthreads();
#pragma unroll
    for (int k = 0; k < 8; ++k) {
        if (rr[k] >= 0) {
            const int e   = base + k * 256 + tid;
            const int pos = atomicAdd(&cur[rr[k]], 1);
            g_edge[pos] = make_int4(__ldg(edges + e), __ldg(edges + E + e), e, 0);
        }
    }
}

// ---- launch 3: fused attn + msg + self-loop, two phases, red.v4, ILP = 4 --------
__global__ void __launch_bounds__(256, 3)
k_main(const float* __restrict__ node_feat,
       const float* __restrict__ ttr,   // [E,32]
       const float* __restrict__ tre,   // [E,32]
       const float* __restrict__ A_w,   // [32,128]
       const float* __restrict__ B_w,   // [32]
       const float* __restrict__ B_b,   // [1]
       float*       __restrict__ out)
{
    const int r     = blockIdx.x;
    const int start = __ldg(&g_off[r]);
    const int end   = __ldg(&g_off[r + 1]);
    if (start >= end) return;            // block-uniform

    const int tid  = threadIdx.x;
    const int lane = tid & 31;

    // are/atr coefficients + rel_w column pairs in smem
    __shared__ u64 sAre[32 * 17];
    __shared__ u64 sAtr[32 * 17];
    __shared__ u64 sRw [16 * 32];         // rel_w[r] packed: [i][lane]
    for (int idx = tid; idx < 32 * 16; idx += 256) {
        const int row = idx >> 4, i = idx & 15;
        sAre[row * 17 + i] = pk2(__ldg(A_w + row * 128 + 64 + 2*i),
                                 __ldg(A_w + row * 128 + 64 + 2*i + 1));
        sAtr[row * 17 + i] = pk2(__ldg(A_w + row * 128 + 96 + 2*i),
                                 __ldg(A_w + row * 128 + 96 + 2*i + 1));
    }
    for (int idx = tid; idx < 512; idx += 256) {
        const int i = idx >> 5, ln = idx & 31;
        sRw[i * 32 + ln] = pk2(__ldg(&g_relw[r * 1024 + i * 64 + ln]),
                               __ldg(&g_relw[r * 1024 + i * 64 + 32 + ln]));
    }
    __syncthreads();

    const float bw = __ldg(B_w + lane);
    const float bb = __ldg(B_b);

    const int w = blockIdx.y * 8 + (tid >> 5);
    const int W = gridDim.y * 8;

    for (int i0 = start + w * 4; i0 < end; i0 += W * 4) {
        int ss[4], tt[4], ee[4];
#pragma unroll
        for (int k = 0; k < 4; ++k) {
            const int4 e4 = __ldg(&g_edge[min(i0 + k, end - 1)]);
            ss[k] = e4.x; tt[k] = e4.y; ee[k] = e4.z;
        }
        float hh[4], sl[4];
#pragma unroll
        for (int k = 0; k < 4; ++k) {
            const float2 hts = __ldg(&g_htsl[(size_t)tt[k] * 32 + lane]);
            hh[k] = __ldg(&g_hs[(size_t)ss[k] * 32 + lane]) + hts.x;
            sl[k] = hts.y;
        }

        // ---- phase 1: attention (aacc freed before phase 2) ----
        float p[4];
        {
            u64 aacc[4] = {0ull, 0ull, 0ull, 0ull};
#pragma unroll
            for (int c = 0; c < 8; ++c) {
                const u64 a0 = sAre[lane * 17 + 2*c];
                const u64 a1 = sAre[lane * 17 + 2*c + 1];
                const u64 t0 = sAtr[lane * 17 + 2*c];
                const u64 t1 = sAtr[lane * 17 + 2*c + 1];
#pragma unroll
                for (int k = 0; k < 4; ++k) {
                    ulonglong2 X = __ldg((const ulonglong2*)(tre + (size_t)ee[k] * 32) + c);
                    ulonglong2 Y = __ldg((const ulonglong2*)(ttr + (size_t)ee[k] * 32) + c);
                    fma2(aacc[k], X.x, a0);  fma2(aacc[k], X.y, a1);
                    fma2(aacc[k], Y.x, t0);  fma2(aacc[k], Y.y, t1);
                }
            }
#pragma unroll
            for (int k = 0; k < 4; ++k)
                p[k] = fmaxf(hh[k] + upk_sum(aacc[k]), 0.f) * bw;
        }
#pragma unroll
        for (int o = 16; o; o >>= 1) {
#pragma unroll
            for (int k = 0; k < 4; ++k)
                p[k] += __shfl_xor_sync(0xffffffffu, p[k], o);
        }
        float att[4];
#pragma unroll
        for (int k = 0; k < 4; ++k)
            att[k] = 1.f / (1.f + __expf(-(p[k] + bb)));

        // ---- phase 2: message ----
        float v[4];
        {
            u64 macc[4] = {0ull, 0ull, 0ull, 0ull};
#pragma unroll
            for (int c = 0; c < 8; ++c) {
                const u64 r0 = sRw[(2*c)     * 32 + lane];
                const u64 r1 = sRw[(2*c + 1) * 32 + lane];
#pragma unroll
                for (int k = 0; k < 4; ++k) {
                    ulonglong2 F = __ldg((const ulonglong2*)(node_feat + (size_t)ss[k] * 32) + c);
                    fma2(macc[k], F.x, r0);
                    fma2(macc[k], F.y, r1);
                }
            }
#pragma unroll
            for (int k = 0; k < 4; ++k)
                v[k] = fmaf(upk_sum(macc[k]), att[k], sl[k]);
        }

        // all 32 lanes issue one red.v4: lane group k = edge k, 8 lanes each
        const int kk = lane >> 3;           // which edge this lane stores
        const int g0 = (lane & 7) * 4;      // feature offset
        float q0 = 0.f, q1 = 0.f, q2 = 0.f, q3 = 0.f;
#pragma unroll
        for (int k = 0; k < 4; ++k) {
            float a  = __shfl_sync(0xffffffffu, v[k], g0 + 0);
            float bq = __shfl_sync(0xffffffffu, v[k], g0 + 1);
            float cq = __shfl_sync(0xffffffffu, v[k], g0 + 2);
            float dq = __shfl_sync(0xffffffffu, v[k], g0 + 3);
            if (kk == k) { q0 = a; q1 = bq; q2 = cq; q3 = dq; }
        }
        if (i0 + kk < end) {
            float* p_ = out + (size_t)tt[kk] * 32 + g0;
            asm volatile("red.global.add.v4.f32 [%0], {%1, %2, %3, %4};"
                         :: "l"(p_), "f"(q0), "f"(q1), "f"(q2), "f"(q3) : "memory");
        }
    }
}

extern "C" void kernel_launch(void* const* d_in, const int* in_sizes, int n_in,
                              void* d_out, int out_size)
{
    const float* node_feat = (const float*)d_in[0];
    const float* ttr       = (const float*)d_in[1];
    const float* tre       = (const float*)d_in[2];
    const float* weight    = (const float*)d_in[3];
    const float* w_comp    = (const float*)d_in[4];
    const float* slw       = (const float*)d_in[5];
    const float* A_w       = (const float*)d_in[6];
    const float* A_b       = (const float*)d_in[7];
    const float* B_w       = (const float*)d_in[8];
    const float* B_b       = (const float*)d_in[9];
    const int*   edges     = (const int*)d_in[10];
    const int*   rels      = (const int*)d_in[11];
    float* out = (float*)d_out;

    const int E  = in_sizes[11];
    const int N  = in_sizes[0] / 32;
    const int NB = in_sizes[3] / 1024;
    const int R  = in_sizes[4] / NB;

    const int nbNode = (N + 63) / 64;
    const int nbHist = (E + 2047) / 2048;
    const int nbZero = (out_size + 1023) / 1024;   // 256 thr * 4 floats

    void* cptr = nullptr;
    cudaGetSymbolAddress(&cptr, g_c);
    cudaMemsetAsync(cptr, 0, sizeof(Counters));

    k_pre<<<R + nbNode + nbHist, 256>>>(weight, w_comp, node_feat, A_w, A_b,
                                        slw, rels, NB, R, N, E, nbNode, nbHist);
    k_scat<<<nbHist + nbZero, 256>>>(edges, rels, out, E, nbHist, out_size);
    k_main<<<dim3(R, 10), 256>>>(node_feat, ttr, tre, A_w, B_w, B_b, out);
}

// round 15
// speedup vs baseline: 1.0164x; 1.0053x over previous
#include <cuda_runtime.h>
#include <cuda_bf16.h>

// ---------------------------------------------------------------------------
// RGCN layer, 3 launches + 1 memset:
//  k_pre  : basis expansion (ILP=4) | node hs + (ht,sl) float2 (A_w smem-staged)
//           | relation histogram + last-block scan
//  k_scat : counting-sort scatter (int4 {src,tgt,eid}) | zero out
//  k_main : per-relation blocks; fused attn+msg+self-loop; contiguous per-warp
//           chunks (L1-resident edge records); shfl reduce; red.v4
// ---------------------------------------------------------------------------

#define RMAX 256
#define NMAX 16384
#define EMAX 262144

typedef unsigned long long u64;

__device__ __forceinline__ u64 pk2(float lo, float hi) {
    u64 r; asm("mov.b64 %0, {%1, %2};" : "=l"(r) : "f"(lo), "f"(hi)); return r;
}
__device__ __forceinline__ void fma2(u64& d, u64 a, u64 b) {
    asm("fma.rn.f32x2 %0, %1, %2, %0;" : "+l"(d) : "l"(a), "l"(b));
}
__device__ __forceinline__ float upk_sum(u64 v) {
    float lo, hi; asm("mov.b64 {%0, %1}, %2;" : "=f"(lo), "=f"(hi) : "l"(v));
    return lo + hi;
}

__device__ float  g_relw[RMAX * 1024];
__device__ float  g_hs[NMAX * 32];
__device__ float2 g_htsl[NMAX * 32];   // interleaved (ht, sl) per node/lane
__device__ int4   g_edge[EMAX];        // sorted {src, tgt, eid, 0}
__device__ int    g_off[RMAX + 1];
__device__ int    g_cur[RMAX];
struct Counters { int cnt[RMAX]; int done; };
__device__ Counters g_c;

// ---- launch 1: basis | node hs/(ht,sl) | rel histogram + scan ------------------
__global__ void __launch_bounds__(256)
k_pre(const float* __restrict__ weight,    // [NB,32,32]
      const float* __restrict__ w_comp,    // [R,NB]
      const float* __restrict__ node_feat, // [N,32]
      const float* __restrict__ A_w,       // [32,128]
      const float* __restrict__ A_b,       // [32]
      const float* __restrict__ slw,       // [32,32]
      const int*   __restrict__ rels,      // [E]
      int NB, int R, int N, int E, int nbNode, int nbHist)
{
    int b = blockIdx.x;
    const int tid = threadIdx.x;

    if (b < R) {                                    // --- basis expansion, ILP=4 ---
        const float* wc = w_comp + b * NB;
        float acc0 = 0.f, acc1 = 0.f, acc2 = 0.f, acc3 = 0.f;
        for (int k = 0; k < NB; ++k) {
            const float wcb = __ldg(wc + k);
            const float* wp = weight + k * 1024 + tid;
            acc0 = fmaf(wcb, __ldg(wp +   0), acc0);
            acc1 = fmaf(wcb, __ldg(wp + 256), acc1);
            acc2 = fmaf(wcb, __ldg(wp + 512), acc2);
            acc3 = fmaf(wcb, __ldg(wp + 768), acc3);
        }
        g_relw[b * 1024 + tid +   0] = acc0;
        g_relw[b * 1024 + tid + 256] = acc1;
        g_relw[b * 1024 + tid + 512] = acc2;
        g_relw[b * 1024 + tid + 768] = acc3;
        return;
    }
    b -= R;

    if (b < nbNode) {                               // --- node hs / (ht,sl) ---
        __shared__ float sA[32 * 129];
        for (int idx = tid; idx < 4096; idx += 256)
            sA[(idx >> 7) * 129 + (idx & 127)] = __ldg(A_w + idx);
        __syncthreads();

        const int lane = tid & 31;
        const int warp = tid >> 5;
        float aws[32], awt[32], slc[32];
#pragma unroll
        for (int i = 0; i < 32; ++i) {
            aws[i] = sA[lane * 129 + i];
            awt[i] = sA[lane * 129 + 32 + i];
            slc[i] = __ldg(slw + i * 32 + lane);    // coalesced
        }
        const float ab = __ldg(A_b + lane);
        // 64 nodes per block, 8 per warp
#pragma unroll
        for (int k = 0; k < 8; ++k) {
            const int n = b * 64 + warp * 8 + k;
            if (n < N) {
                const float4* fp = (const float4*)(node_feat + (size_t)n * 32);
                float hs = ab, ht = 0.f, sl = 0.f;
#pragma unroll
                for (int c = 0; c < 8; ++c) {
                    float4 f = __ldg(fp + c);
                    hs = fmaf(f.x, aws[4*c+0], hs); ht = fmaf(f.x, awt[4*c+0], ht); sl = fmaf(f.x, slc[4*c+0], sl);
                    hs = fmaf(f.y, aws[4*c+1], hs); ht = fmaf(f.y, awt[4*c+1], ht); sl = fmaf(f.y, slc[4*c+1], sl);
                    hs = fmaf(f.z, aws[4*c+2], hs); ht = fmaf(f.z, awt[4*c+2], ht); sl = fmaf(f.z, slc[4*c+2], sl);
                    hs = fmaf(f.w, aws[4*c+3], hs); ht = fmaf(f.w, awt[4*c+3], ht); sl = fmaf(f.w, slc[4*c+3], sl);
                }
                g_hs[(size_t)n * 32 + lane]   = hs;
                g_htsl[(size_t)n * 32 + lane] = make_float2(ht, sl);
            }
        }
        return;
    }
    b -= nbNode;

    // --- relation histogram (2048 edges/block) + last-block scan ---
    __shared__ int sh[RMAX];
    for (int i = tid; i < RMAX; i += 256) sh[i] = 0;
    __syncthreads();
    const int base = b * 2048;
#pragma unroll
    for (int k = 0; k < 8; ++k) {
        const int e = base + k * 256 + tid;
        if (e < E) atomicAdd(&sh[__ldg(rels + e)], 1);
    }
    __syncthreads();
    for (int i = tid; i < RMAX; i += 256) {
        const int v = sh[i];
        if (v) atomicAdd(&g_c.cnt[i], v);
    }
    __threadfence();
    __syncthreads();
    __shared__ int s_last;
    if (tid == 0)
        s_last = (atomicAdd(&g_c.done, 1) == nbHist - 1);
    __syncthreads();
    if (s_last) {                                   // --- last block: scan ---
        __shared__ int buf[RMAX];
        const int c = atomicAdd(&g_c.cnt[tid], 0);  // coherent read
        buf[tid] = c;
        __syncthreads();
#pragma unroll
        for (int d = 1; d < RMAX; d <<= 1) {
            const int v = (tid >= d) ? buf[tid - d] : 0;
            __syncthreads();
            buf[tid] += v;
            __syncthreads();
        }
        if (tid == 0) g_off[0] = 0;
        g_off[tid + 1] = buf[tid];
        g_cur[tid]     = buf[tid] - c;              // exclusive
    }
}

// ---- launch 2: counting-sort scatter | zero out ----------------------------------
__global__ void __launch_bounds__(256)
k_scat(const int* __restrict__ edges,  // [2,E]
       const int* __restrict__ rels,   // [E]
       float*     __restrict__ out,
       int E, int nbHist, int out_sz)
{
    int b = blockIdx.x;
    const int tid = threadIdx.x;

    if (b >= nbHist) {                              // --- zero out blocks ---
        b -= nbHist;
        const int i0 = (b * 256 + tid) * 4;
        if (i0 + 3 < out_sz)
            *(float4*)(out + i0) = make_float4(0.f, 0.f, 0.f, 0.f);
        else
            for (int i = i0; i < out_sz; ++i) out[i] = 0.f;
        return;
    }

    __shared__ int h[RMAX];
    __shared__ int cur[RMAX];
    for (int i = tid; i < RMAX; i += 256) h[i] = 0;
    __syncthreads();
    const int base = b * 2048;
    int rr[8];
#pragma unroll
    for (int k = 0; k < 8; ++k) {
        const int e = base + k * 256 + tid;
        rr[k] = (e < E) ? __ldg(rels + e) : -1;
        if (rr[k] >= 0) atomicAdd(&h[rr[k]], 1);
    }
    __syncthreads();
    for (int i = tid; i < RMAX; i += 256) {
        const int v = h[i];
        cur[i] = v ? atomicAdd(&g_cur[i], v) : 0;
    }
    __syncthreads();
#pragma unroll
    for (int k = 0; k < 8; ++k) {
        if (rr[k] >= 0) {
            const int e   = base + k * 256 + tid;
            const int pos = atomicAdd(&cur[rr[k]], 1);
            g_edge[pos] = make_int4(__ldg(edges + e), __ldg(edges + E + e), e, 0);
        }
    }
}

// ---- launch 3: fused attn+msg+self-loop, contiguous chunks, red.v4 --------------
__global__ void __launch_bounds__(256)
k_main(const float* __restrict__ node_feat,
       const float* __restrict__ ttr,   // [E,32]
       const float* __restrict__ tre,   // [E,32]
       const float* __restrict__ A_w,   // [32,128]
       const float* __restrict__ B_w,   // [32]
       const float* __restrict__ B_b,   // [1]
       float*       __restrict__ out)
{
    const int r     = blockIdx.x;
    const int start = __ldg(&g_off[r]);
    const int end   = __ldg(&g_off[r + 1]);
    if (start >= end) return;            // block-uniform

    const int tid  = threadIdx.x;
    const int lane = tid & 31;

    // are/atr coefficients + rel_w column pairs in smem
    __shared__ u64 sAre[32 * 17];
    __shared__ u64 sAtr[32 * 17];
    __shared__ u64 sRw [16 * 32];         // rel_w[r] packed: [i][lane]
    for (int idx = tid; idx < 32 * 16; idx += 256) {
        const int row = idx >> 4, i = idx & 15;
        sAre[row * 17 + i] = pk2(__ldg(A_w + row * 128 + 64 + 2*i),
                                 __ldg(A_w + row * 128 + 64 + 2*i + 1));
        sAtr[row * 17 + i] = pk2(__ldg(A_w + row * 128 + 96 + 2*i),
                                 __ldg(A_w + row * 128 + 96 + 2*i + 1));
    }
    for (int idx = tid; idx < 512; idx += 256) {
        const int i = idx >> 5, ln = idx & 31;
        sRw[i * 32 + ln] = pk2(__ldg(&g_relw[r * 1024 + i * 64 + ln]),
                               __ldg(&g_relw[r * 1024 + i * 64 + 32 + ln]));
    }
    __syncthreads();

    const float bw = __ldg(B_w + lane);
    const float bb = __ldg(B_b);

    // contiguous per-warp chunk of this relation's bucket
    const int wid = blockIdx.y * 8 + (tid >> 5);
    const int W   = gridDim.y * 8;
    const int cnt = end - start;
    const int chunk = (((cnt + W - 1) / W) + 3) & ~3;   // multiple of 4
    int i0 = start + wid * chunk;
    const int iend = min(i0 + chunk, end);

    for (; i0 < iend; i0 += 4) {
        int ss[4], tt[4], ee[4];
#pragma unroll
        for (int k = 0; k < 4; ++k) {
            const int4 e4 = __ldg(&g_edge[min(i0 + k, end - 1)]);
            ss[k] = e4.x; tt[k] = e4.y; ee[k] = e4.z;
        }
        float hh[4], sl[4];
#pragma unroll
        for (int k = 0; k < 4; ++k) {
            const float2 hts = __ldg(&g_htsl[(size_t)tt[k] * 32 + lane]);
            hh[k] = __ldg(&g_hs[(size_t)ss[k] * 32 + lane]) + hts.x;
            sl[k] = hts.y;
        }

        // ---- phase 1: attention ----
        float p[4];
        {
            u64 aacc[4] = {0ull, 0ull, 0ull, 0ull};
#pragma unroll
            for (int c = 0; c < 8; ++c) {
                const u64 a0 = sAre[lane * 17 + 2*c];
                const u64 a1 = sAre[lane * 17 + 2*c + 1];
                const u64 t0 = sAtr[lane * 17 + 2*c];
                const u64 t1 = sAtr[lane * 17 + 2*c + 1];
#pragma unroll
                for (int k = 0; k < 4; ++k) {
                    ulonglong2 X = __ldg((const ulonglong2*)(tre + (size_t)ee[k] * 32) + c);
                    ulonglong2 Y = __ldg((const ulonglong2*)(ttr + (size_t)ee[k] * 32) + c);
                    fma2(aacc[k], X.x, a0);  fma2(aacc[k], X.y, a1);
                    fma2(aacc[k], Y.x, t0);  fma2(aacc[k], Y.y, t1);
                }
            }
#pragma unroll
            for (int k = 0; k < 4; ++k)
                p[k] = fmaxf(hh[k] + upk_sum(aacc[k]), 0.f) * bw;
        }
#pragma unroll
        for (int o = 16; o; o >>= 1) {
#pragma unroll
            for (int k = 0; k < 4; ++k)
                p[k] += __shfl_xor_sync(0xffffffffu, p[k], o);
        }
        float att[4];
#pragma unroll
        for (int k = 0; k < 4; ++k)
            att[k] = 1.f / (1.f + __expf(-(p[k] + bb)));

        // ---- phase 2: message ----
        float v[4];
        {
            u64 macc[4] = {0ull, 0ull, 0ull, 0ull};
#pragma unroll
            for (int c = 0; c < 8; ++c) {
                const u64 r0 = sRw[(2*c)     * 32 + lane];
                const u64 r1 = sRw[(2*c + 1) * 32 + lane];
#pragma unroll
                for (int k = 0; k < 4; ++k) {
                    ulonglong2 F = __ldg((const ulonglong2*)(node_feat + (size_t)ss[k] * 32) + c);
                    fma2(macc[k], F.x, r0);
                    fma2(macc[k], F.y, r1);
                }
            }
#pragma unroll
            for (int k = 0; k < 4; ++k)
                v[k] = fmaf(upk_sum(macc[k]), att[k], sl[k]);
        }

        // all 32 lanes issue one red.v4: lane group k = edge k, 8 lanes each
        const int kk = lane >> 3;           // which edge this lane stores
        const int g0 = (lane & 7) * 4;      // feature offset
        float q0 = 0.f, q1 = 0.f, q2 = 0.f, q3 = 0.f;
#pragma unroll
        for (int k = 0; k < 4; ++k) {
            float a  = __shfl_sync(0xffffffffu, v[k], g0 + 0);
            float bq = __shfl_sync(0xffffffffu, v[k], g0 + 1);
            float cq = __shfl_sync(0xffffffffu, v[k], g0 + 2);
            float dq = __shfl_sync(0xffffffffu, v[k], g0 + 3);
            if (kk == k) { q0 = a; q1 = bq; q2 = cq; q3 = dq; }
        }
        if (i0 + kk < iend) {               // chunk-bounded: no double count
            float* p_ = out + (size_t)tt[kk] * 32 + g0;
            asm volatile("red.global.add.v4.f32 [%0], {%1, %2, %3, %4};"
                         :: "l"(p_), "f"(q0), "f"(q1), "f"(q2), "f"(q3) : "memory");
        }
    }
}

extern "C" void kernel_launch(void* const* d_in, const int* in_sizes, int n_in,
                              void* d_out, int out_size)
{
    const float* node_feat = (const float*)d_in[0];
    const float* ttr       = (const float*)d_in[1];
    const float* tre       = (const float*)d_in[2];
    const float* weight    = (const float*)d_in[3];
    const float* w_comp    = (const float*)d_in[4];
    const float* slw       = (const float*)d_in[5];
    const float* A_w       = (const float*)d_in[6];
    const float* A_b       = (const float*)d_in[7];
    const float* B_w       = (const float*)d_in[8];
    const float* B_b       = (const float*)d_in[9];
    const int*   edges     = (const int*)d_in[10];
    const int*   rels      = (const int*)d_in[11];
    float* out = (float*)d_out;

    const int E  = in_sizes[11];
    const int N  = in_sizes[0] / 32;
    const int NB = in_sizes[3] / 1024;
    const int R  = in_sizes[4] / NB;

    const int nbNode = (N + 63) / 64;
    const int nbHist = (E + 2047) / 2048;
    const int nbZero = (out_size + 1023) / 1024;   // 256 thr * 4 floats

    void* cptr = nullptr;
    cudaGetSymbolAddress(&cptr, g_c);
    cudaMemsetAsync(cptr, 0, sizeof(Counters));

    k_pre<<<R + nbNode + nbHist, 256>>>(weight, w_comp, node_feat, A_w, A_b,
                                        slw, rels, NB, R, N, E, nbNode, nbHist);
    k_scat<<<nbHist + nbZero, 256>>>(edges, rels, out, E, nbHist, out_size);
    k_main<<<dim3(R, 10), 256>>>(node_feat, ttr, tre, A_w, B_w, B_b, out);
}

// round 16
// speedup vs baseline: 1.0424x; 1.0255x over previous
#include <cuda_runtime.h>
#include <cuda_bf16.h>

// ---------------------------------------------------------------------------
// RGCN layer, 3 launches + 1 memset:
//  k_pre  : basis expansion (ILP=4) | node hs + (ht,sl) float2 (A_w smem-staged)
//           | relation histogram + last-block scan
//  k_scat : counting-sort scatter (int4 {src,tgt,eid}) | zero out
//  k_main : per-relation blocks; fused attn+msg+self-loop; edge rows staged
//           coalesced through smem (broadcast LDS compute); red.v4
// ---------------------------------------------------------------------------

#define RMAX 256
#define NMAX 16384
#define EMAX 262144

typedef unsigned long long u64;

__device__ __forceinline__ u64 pk2(float lo, float hi) {
    u64 r; asm("mov.b64 %0, {%1, %2};" : "=l"(r) : "f"(lo), "f"(hi)); return r;
}
__device__ __forceinline__ void fma2(u64& d, u64 a, u64 b) {
    asm("fma.rn.f32x2 %0, %1, %2, %0;" : "+l"(d) : "l"(a), "l"(b));
}
__device__ __forceinline__ float upk_sum(u64 v) {
    float lo, hi; asm("mov.b64 {%0, %1}, %2;" : "=f"(lo), "=f"(hi) : "l"(v));
    return lo + hi;
}

__device__ float  g_relw[RMAX * 1024];
__device__ float  g_hs[NMAX * 32];
__device__ float2 g_htsl[NMAX * 32];   // interleaved (ht, sl) per node/lane
__device__ int4   g_edge[EMAX];        // sorted {src, tgt, eid, 0}
__device__ int    g_off[RMAX + 1];
__device__ int    g_cur[RMAX];
struct Counters { int cnt[RMAX]; int done; };
__device__ Counters g_c;

// ---- launch 1: basis | node hs/(ht,sl) | rel histogram + scan ------------------
__global__ void __launch_bounds__(256)
k_pre(const float* __restrict__ weight,    // [NB,32,32]
      const float* __restrict__ w_comp,    // [R,NB]
      const float* __restrict__ node_feat, // [N,32]
      const float* __restrict__ A_w,       // [32,128]
      const float* __restrict__ A_b,       // [32]
      const float* __restrict__ slw,       // [32,32]
      const int*   __restrict__ rels,      // [E]
      int NB, int R, int N, int E, int nbNode, int nbHist)
{
    int b = blockIdx.x;
    const int tid = threadIdx.x;

    if (b < R) {                                    // --- basis expansion, ILP=4 ---
        const float* wc = w_comp + b * NB;
        float acc0 = 0.f, acc1 = 0.f, acc2 = 0.f, acc3 = 0.f;
        for (int k = 0; k < NB; ++k) {
            const float wcb = __ldg(wc + k);
            const float* wp = weight + k * 1024 + tid;
            acc0 = fmaf(wcb, __ldg(wp +   0), acc0);
            acc1 = fmaf(wcb, __ldg(wp + 256), acc1);
            acc2 = fmaf(wcb, __ldg(wp + 512), acc2);
            acc3 = fmaf(wcb, __ldg(wp + 768), acc3);
        }
        g_relw[b * 1024 + tid +   0] = acc0;
        g_relw[b * 1024 + tid + 256] = acc1;
        g_relw[b * 1024 + tid + 512] = acc2;
        g_relw[b * 1024 + tid + 768] = acc3;
        return;
    }
    b -= R;

    if (b < nbNode) {                               // --- node hs / (ht,sl) ---
        __shared__ float sA[32 * 129];
        for (int idx = tid; idx < 4096; idx += 256)
            sA[(idx >> 7) * 129 + (idx & 127)] = __ldg(A_w + idx);
        __syncthreads();

        const int lane = tid & 31;
        const int warp = tid >> 5;
        float aws[32], awt[32], slc[32];
#pragma unroll
        for (int i = 0; i < 32; ++i) {
            aws[i] = sA[lane * 129 + i];
            awt[i] = sA[lane * 129 + 32 + i];
            slc[i] = __ldg(slw + i * 32 + lane);    // coalesced
        }
        const float ab = __ldg(A_b + lane);
        // 64 nodes per block, 8 per warp
#pragma unroll
        for (int k = 0; k < 8; ++k) {
            const int n = b * 64 + warp * 8 + k;
            if (n < N) {
                const float4* fp = (const float4*)(node_feat + (size_t)n * 32);
                float hs = ab, ht = 0.f, sl = 0.f;
#pragma unroll
                for (int c = 0; c < 8; ++c) {
                    float4 f = __ldg(fp + c);
                    hs = fmaf(f.x, aws[4*c+0], hs); ht = fmaf(f.x, awt[4*c+0], ht); sl = fmaf(f.x, slc[4*c+0], sl);
                    hs = fmaf(f.y, aws[4*c+1], hs); ht = fmaf(f.y, awt[4*c+1], ht); sl = fmaf(f.y, slc[4*c+1], sl);
                    hs = fmaf(f.z, aws[4*c+2], hs); ht = fmaf(f.z, awt[4*c+2], ht); sl = fmaf(f.z, slc[4*c+2], sl);
                    hs = fmaf(f.w, aws[4*c+3], hs); ht = fmaf(f.w, awt[4*c+3], ht); sl = fmaf(f.w, slc[4*c+3], sl);
                }
                g_hs[(size_t)n * 32 + lane]   = hs;
                g_htsl[(size_t)n * 32 + lane] = make_float2(ht, sl);
            }
        }
        return;
    }
    b -= nbNode;

    // --- relation histogram (2048 edges/block) + last-block scan ---
    __shared__ int sh[RMAX];
    for (int i = tid; i < RMAX; i += 256) sh[i] = 0;
    __syncthreads();
    const int base = b * 2048;
#pragma unroll
    for (int k = 0; k < 8; ++k) {
        const int e = base + k * 256 + tid;
        if (e < E) atomicAdd(&sh[__ldg(rels + e)], 1);
    }
    __syncthreads();
    for (int i = tid; i < RMAX; i += 256) {
        const int v = sh[i];
        if (v) atomicAdd(&g_c.cnt[i], v);
    }
    __threadfence();
    __syncthreads();
    __shared__ int s_last;
    if (tid == 0)
        s_last = (atomicAdd(&g_c.done, 1) == nbHist - 1);
    __syncthreads();
    if (s_last) {                                   // --- last block: scan ---
        __shared__ int buf[RMAX];
        const int c = atomicAdd(&g_c.cnt[tid], 0);  // coherent read
        buf[tid] = c;
        __syncthreads();
#pragma unroll
        for (int d = 1; d < RMAX; d <<= 1) {
            const int v = (tid >= d) ? buf[tid - d] : 0;
            __syncthreads();
            buf[tid] += v;
            __syncthreads();
        }
        if (tid == 0) g_off[0] = 0;
        g_off[tid + 1] = buf[tid];
        g_cur[tid]     = buf[tid] - c;              // exclusive
    }
}

// ---- launch 2: counting-sort scatter | zero out ----------------------------------
__global__ void __launch_bounds__(256)
k_scat(const int* __restrict__ edges,  // [2,E]
       const int* __restrict__ rels,   // [E]
       float*     __restrict__ out,
       int E, int nbHist, int out_sz)
{
    int b = blockIdx.x;
    const int tid = threadIdx.x;

    if (b >= nbHist) {                              // --- zero out blocks ---
        b -= nbHist;
        const int i0 = (b * 256 + tid) * 4;
        if (i0 + 3 < out_sz)
            *(float4*)(out + i0) = make_float4(0.f, 0.f, 0.f, 0.f);
        else
            for (int i = i0; i < out_sz; ++i) out[i] = 0.f;
        return;
    }

    __shared__ int h[RMAX];
    __shared__ int cur[RMAX];
    for (int i = tid; i < RMAX; i += 256) h[i] = 0;
    __syncthreads();
    const int base = b * 2048;
    int rr[8];
#pragma unroll
    for (int k = 0; k < 8; ++k) {
        const int e = base + k * 256 + tid;
        rr[k] = (e < E) ? __ldg(rels + e) : -1;
        if (rr[k] >= 0) atomicAdd(&h[rr[k]], 1);
    }
    __syncthreads();
    for (int i = tid; i < RMAX; i += 256) {
        const int v = h[i];
        cur[i] = v ? atomicAdd(&g_cur[i], v) : 0;
    }
    __syncthreads();
#pragma unroll
    for (int k = 0; k < 8; ++k) {
        if (rr[k] >= 0) {
            const int e   = base + k * 256 + tid;
            const int pos = atomicAdd(&cur[rr[k]], 1);
            g_edge[pos] = make_int4(__ldg(edges + e), __ldg(edges + E + e), e, 0);
        }
    }
}

// ---- launch 3: fused attn+msg+self-loop; smem-staged edge rows; red.v4 ----------
__global__ void __launch_bounds__(256)
k_main(const float* __restrict__ node_feat,
       const float* __restrict__ ttr,   // [E,32]
       const float* __restrict__ tre,   // [E,32]
       const float* __restrict__ A_w,   // [32,128]
       const float* __restrict__ B_w,   // [32]
       const float* __restrict__ B_b,   // [1]
       float*       __restrict__ out)
{
    const int r     = blockIdx.x;
    const int start = __ldg(&g_off[r]);
    const int end   = __ldg(&g_off[r + 1]);
    if (start >= end) return;            // block-uniform

    const int tid  = threadIdx.x;
    const int lane = tid & 31;
    const int wslot = tid >> 5;          // warp within block (0..7)

    // are/atr coefficients + rel_w column pairs in smem
    __shared__ u64 sAre[32 * 17];
    __shared__ u64 sAtr[32 * 17];
    __shared__ u64 sRw [16 * 32];         // rel_w[r] packed: [i][lane]
    // per-warp staging for 4 edges x {tre,ttr,feat} rows (32 floats each)
    __shared__ float sX[8][4][32];
    __shared__ float sY[8][4][32];
    __shared__ float sF[8][4][32];

    for (int idx = tid; idx < 32 * 16; idx += 256) {
        const int row = idx >> 4, i = idx & 15;
        sAre[row * 17 + i] = pk2(__ldg(A_w + row * 128 + 64 + 2*i),
                                 __ldg(A_w + row * 128 + 64 + 2*i + 1));
        sAtr[row * 17 + i] = pk2(__ldg(A_w + row * 128 + 96 + 2*i),
                                 __ldg(A_w + row * 128 + 96 + 2*i + 1));
    }
    for (int idx = tid; idx < 512; idx += 256) {
        const int i = idx >> 5, ln = idx & 31;
        sRw[i * 32 + ln] = pk2(__ldg(&g_relw[r * 1024 + i * 64 + ln]),
                               __ldg(&g_relw[r * 1024 + i * 64 + 32 + ln]));
    }
    __syncthreads();

    const float bw = __ldg(B_w + lane);
    const float bb = __ldg(B_b);

    const int w = blockIdx.y * 8 + wslot;
    const int W = gridDim.y * 8;

    for (int i0 = start + w * 4; i0 < end; i0 += W * 4) {
        int ss[4], tt[4], ee[4];
#pragma unroll
        for (int k = 0; k < 4; ++k) {
            const int4 e4 = __ldg(&g_edge[min(i0 + k, end - 1)]);
            ss[k] = e4.x; tt[k] = e4.y; ee[k] = e4.z;
        }
        float hh[4], sl[4];
#pragma unroll
        for (int k = 0; k < 4; ++k) {
            const float2 hts = __ldg(&g_htsl[(size_t)tt[k] * 32 + lane]);
            hh[k] = __ldg(&g_hs[(size_t)ss[k] * 32 + lane]) + hts.x;
            sl[k] = hts.y;
        }

        // ---- coalesced staging: lane = element index, 12 wavefronts total ----
        __syncwarp();    // previous iteration's smem reads complete
#pragma unroll
        for (int k = 0; k < 4; ++k) {
            sX[wslot][k][lane] = __ldg(tre + (size_t)ee[k] * 32 + lane);
            sY[wslot][k][lane] = __ldg(ttr + (size_t)ee[k] * 32 + lane);
            sF[wslot][k][lane] = __ldg(node_feat + (size_t)ss[k] * 32 + lane);
        }
        __syncwarp();

        // ---- phase 1: attention (broadcast LDS reads) ----
        float p[4];
        {
            u64 aacc[4] = {0ull, 0ull, 0ull, 0ull};
#pragma unroll
            for (int c = 0; c < 8; ++c) {
                const u64 a0 = sAre[lane * 17 + 2*c];
                const u64 a1 = sAre[lane * 17 + 2*c + 1];
                const u64 t0 = sAtr[lane * 17 + 2*c];
                const u64 t1 = sAtr[lane * 17 + 2*c + 1];
#pragma unroll
                for (int k = 0; k < 4; ++k) {
                    const ulonglong2 X = *((const ulonglong2*)&sX[wslot][k][0] + c);
                    const ulonglong2 Y = *((const ulonglong2*)&sY[wslot][k][0] + c);
                    fma2(aacc[k], X.x, a0);  fma2(aacc[k], X.y, a1);
                    fma2(aacc[k], Y.x, t0);  fma2(aacc[k], Y.y, t1);
                }
            }
#pragma unroll
            for (int k = 0; k < 4; ++k)
                p[k] = fmaxf(hh[k] + upk_sum(aacc[k]), 0.f) * bw;
        }
#pragma unroll
        for (int o = 16; o; o >>= 1) {
#pragma unroll
            for (int k = 0; k < 4; ++k)
                p[k] += __shfl_xor_sync(0xffffffffu, p[k], o);
        }
        float att[4];
#pragma unroll
        for (int k = 0; k < 4; ++k)
            att[k] = 1.f / (1.f + __expf(-(p[k] + bb)));

        // ---- phase 2: message ----
        float v[4];
        {
            u64 macc[4] = {0ull, 0ull, 0ull, 0ull};
#pragma unroll
            for (int c = 0; c < 8; ++c) {
                const u64 r0 = sRw[(2*c)     * 32 + lane];
                const u64 r1 = sRw[(2*c + 1) * 32 + lane];
#pragma unroll
                for (int k = 0; k < 4; ++k) {
                    const ulonglong2 F = *((const ulonglong2*)&sF[wslot][k][0] + c);
                    fma2(macc[k], F.x, r0);
                    fma2(macc[k], F.y, r1);
                }
            }
#pragma unroll
            for (int k = 0; k < 4; ++k)
                v[k] = fmaf(upk_sum(macc[k]), att[k], sl[k]);
        }

        // all 32 lanes issue one red.v4: lane group k = edge k, 8 lanes each
        const int kk = lane >> 3;           // which edge this lane stores
        const int g0 = (lane & 7) * 4;      // feature offset
        float q0 = 0.f, q1 = 0.f, q2 = 0.f, q3 = 0.f;
#pragma unroll
        for (int k = 0; k < 4; ++k) {
            float a  = __shfl_sync(0xffffffffu, v[k], g0 + 0);
            float bq = __shfl_sync(0xffffffffu, v[k], g0 + 1);
            float cq = __shfl_sync(0xffffffffu, v[k], g0 + 2);
            float dq = __shfl_sync(0xffffffffu, v[k], g0 + 3);
            if (kk == k) { q0 = a; q1 = bq; q2 = cq; q3 = dq; }
        }
        if (i0 + kk < end) {
            float* p_ = out + (size_t)tt[kk] * 32 + g0;
            asm volatile("red.global.add.v4.f32 [%0], {%1, %2, %3, %4};"
                         :: "l"(p_), "f"(q0), "f"(q1), "f"(q2), "f"(q3) : "memory");
        }
    }
}

extern "C" void kernel_launch(void* const* d_in, const int* in_sizes, int n_in,
                              void* d_out, int out_size)
{
    const float* node_feat = (const float*)d_in[0];
    const float* ttr       = (const float*)d_in[1];
    const float* tre       = (const float*)d_in[2];
    const float* weight    = (const float*)d_in[3];
    const float* w_comp    = (const float*)d_in[4];
    const float* slw       = (const float*)d_in[5];
    const float* A_w       = (const float*)d_in[6];
    const float* A_b       = (const float*)d_in[7];
    const float* B_w       = (const float*)d_in[8];
    const float* B_b       = (const float*)d_in[9];
    const int*   edges     = (const int*)d_in[10];
    const int*   rels      = (const int*)d_in[11];
    float* out = (float*)d_out;

    const int E  = in_sizes[11];
    const int N  = in_sizes[0] / 32;
    const int NB = in_sizes[3] / 1024;
    const int R  = in_sizes[4] / NB;

    const int nbNode = (N + 63) / 64;
    const int nbHist = (E + 2047) / 2048;
    const int nbZero = (out_size + 1023) / 1024;   // 256 thr * 4 floats

    void* cptr = nullptr;
    cudaGetSymbolAddress(&cptr, g_c);
    cudaMemsetAsync(cptr, 0, sizeof(Counters));

    k_pre<<<R + nbNode + nbHist, 256>>>(weight, w_comp, node_feat, A_w, A_b,
                                        slw, rels, NB, R, N, E, nbNode, nbHist);
    k_scat<<<nbHist + nbZero, 256>>>(edges, rels, out, E, nbHist, out_size);
    k_main<<<dim3(R, 10), 256>>>(node_feat, ttr, tre, A_w, B_w, B_b, out);
}

// round 17
// speedup vs baseline: 1.4115x; 1.3541x over previous
#include <cuda_runtime.h>
#include <cuda_bf16.h>

// ---------------------------------------------------------------------------
// RGCN layer, 3 launches + 1 memset:
//  k_pre  : basis expansion (ILP=4) | node hs + (ht,sl) float2 (A_w half-staged)
//           | relation histogram + last-block scan
//  k_scat : counting-sort scatter (int4 {src,tgt,eid}, 1024/blk) | zero out
//  k_main : per-relation blocks (y=6); fused attn+msg+self-loop; edge rows
//           staged coalesced through smem; red.v4
// ---------------------------------------------------------------------------

#define RMAX 256
#define NMAX 16384
#define EMAX 262144

typedef unsigned long long u64;

__device__ __forceinline__ u64 pk2(float lo, float hi) {
    u64 r; asm("mov.b64 %0, {%1, %2};" : "=l"(r) : "f"(lo), "f"(hi)); return r;
}
__device__ __forceinline__ void fma2(u64& d, u64 a, u64 b) {
    asm("fma.rn.f32x2 %0, %1, %2, %0;" : "+l"(d) : "l"(a), "l"(b));
}
__device__ __forceinline__ float upk_sum(u64 v) {
    float lo, hi; asm("mov.b64 {%0, %1}, %2;" : "=f"(lo), "=f"(hi) : "l"(v));
    return lo + hi;
}

__device__ float  g_relw[RMAX * 1024];
__device__ float  g_hs[NMAX * 32];
__device__ float2 g_htsl[NMAX * 32];   // interleaved (ht, sl) per node/lane
__device__ int4   g_edge[EMAX];        // sorted {src, tgt, eid, 0}
__device__ int    g_off[RMAX + 1];
__device__ int    g_cur[RMAX];
struct Counters { int cnt[RMAX]; int done; };
__device__ Counters g_c;

// ---- launch 1: basis | node hs/(ht,sl) | rel histogram + scan ------------------
__global__ void __launch_bounds__(256)
k_pre(const float* __restrict__ weight,    // [NB,32,32]
      const float* __restrict__ w_comp,    // [R,NB]
      const float* __restrict__ node_feat, // [N,32]
      const float* __restrict__ A_w,       // [32,128]
      const float* __restrict__ A_b,       // [32]
      const float* __restrict__ slw,       // [32,32]
      const int*   __restrict__ rels,      // [E]
      int NB, int R, int N, int E, int nbNode, int nbHist)
{
    int b = blockIdx.x;
    const int tid = threadIdx.x;

    if (b < R) {                                    // --- basis expansion, ILP=4 ---
        const float* wc = w_comp + b * NB;
        float acc0 = 0.f, acc1 = 0.f, acc2 = 0.f, acc3 = 0.f;
        for (int k = 0; k < NB; ++k) {
            const float wcb = __ldg(wc + k);
            const float* wp = weight + k * 1024 + tid;
            acc0 = fmaf(wcb, __ldg(wp +   0), acc0);
            acc1 = fmaf(wcb, __ldg(wp + 256), acc1);
            acc2 = fmaf(wcb, __ldg(wp + 512), acc2);
            acc3 = fmaf(wcb, __ldg(wp + 768), acc3);
        }
        g_relw[b * 1024 + tid +   0] = acc0;
        g_relw[b * 1024 + tid + 256] = acc1;
        g_relw[b * 1024 + tid + 512] = acc2;
        g_relw[b * 1024 + tid + 768] = acc3;
        return;
    }
    b -= R;

    if (b < nbNode) {                               // --- node hs / (ht,sl) ---
        // stage only A_w columns 0..63 (src/tgt halves), pitch 65 conflict-free
        __shared__ float sA[32 * 65];
        for (int idx = tid; idx < 2048; idx += 256) {
            const int row = idx >> 6, col = idx & 63;
            sA[row * 65 + col] = __ldg(A_w + row * 128 + col);
        }
        __syncthreads();

        const int lane = tid & 31;
        const int warp = tid >> 5;
        float aws[32], awt[32], slc[32];
#pragma unroll
        for (int i = 0; i < 32; ++i) {
            aws[i] = sA[lane * 65 + i];
            awt[i] = sA[lane * 65 + 32 + i];
            slc[i] = __ldg(slw + i * 32 + lane);    // coalesced
        }
        const float ab = __ldg(A_b + lane);
        // 64 nodes per block, 8 per warp
#pragma unroll
        for (int k = 0; k < 8; ++k) {
            const int n = b * 64 + warp * 8 + k;
            if (n < N) {
                const float4* fp = (const float4*)(node_feat + (size_t)n * 32);
                float hs = ab, ht = 0.f, sl = 0.f;
#pragma unroll
                for (int c = 0; c < 8; ++c) {
                    float4 f = __ldg(fp + c);
                    hs = fmaf(f.x, aws[4*c+0], hs); ht = fmaf(f.x, awt[4*c+0], ht); sl = fmaf(f.x, slc[4*c+0], sl);
                    hs = fmaf(f.y, aws[4*c+1], hs); ht = fmaf(f.y, awt[4*c+1], ht); sl = fmaf(f.y, slc[4*c+1], sl);
                    hs = fmaf(f.z, aws[4*c+2], hs); ht = fmaf(f.z, awt[4*c+2], ht); sl = fmaf(f.z, slc[4*c+2], sl);
                    hs = fmaf(f.w, aws[4*c+3], hs); ht = fmaf(f.w, awt[4*c+3], ht); sl = fmaf(f.w, slc[4*c+3], sl);
                }
                g_hs[(size_t)n * 32 + lane]   = hs;
                g_htsl[(size_t)n * 32 + lane] = make_float2(ht, sl);
            }
        }
        return;
    }
    b -= nbNode;

    // --- relation histogram (2048 edges/block) + last-block scan ---
    __shared__ int sh[RMAX];
    for (int i = tid; i < RMAX; i += 256) sh[i] = 0;
    __syncthreads();
    const int base = b * 2048;
#pragma unroll
    for (int k = 0; k < 8; ++k) {
        const int e = base + k * 256 + tid;
        if (e < E) atomicAdd(&sh[__ldg(rels + e)], 1);
    }
    __syncthreads();
    for (int i = tid; i < RMAX; i += 256) {
        const int v = sh[i];
        if (v) atomicAdd(&g_c.cnt[i], v);
    }
    __threadfence();
    __syncthreads();
    __shared__ int s_last;
    if (tid == 0)
        s_last = (atomicAdd(&g_c.done, 1) == nbHist - 1);
    __syncthreads();
    if (s_last) {                                   // --- last block: scan ---
        __shared__ int buf[RMAX];
        const int c = atomicAdd(&g_c.cnt[tid], 0);  // coherent read
        buf[tid] = c;
        __syncthreads();
#pragma unroll
        for (int d = 1; d < RMAX; d <<= 1) {
            const int v = (tid >= d) ? buf[tid - d] : 0;
            __syncthreads();
            buf[tid] += v;
            __syncthreads();
        }
        if (tid == 0) g_off[0] = 0;
        g_off[tid + 1] = buf[tid];
        g_cur[tid]     = buf[tid] - c;              // exclusive
    }
}

// ---- launch 2: counting-sort scatter (1024/blk) | zero out -----------------------
__global__ void __launch_bounds__(256)
k_scat(const int* __restrict__ edges,  // [2,E]
       const int* __restrict__ rels,   // [E]
       float*     __restrict__ out,
       int E, int nbScat, int out_sz)
{
    int b = blockIdx.x;
    const int tid = threadIdx.x;

    if (b >= nbScat) {                              // --- zero out blocks ---
        b -= nbScat;
        const int i0 = (b * 256 + tid) * 4;
        if (i0 + 3 < out_sz)
            *(float4*)(out + i0) = make_float4(0.f, 0.f, 0.f, 0.f);
        else
            for (int i = i0; i < out_sz; ++i) out[i] = 0.f;
        return;
    }

    __shared__ int h[RMAX];
    __shared__ int cur[RMAX];
    for (int i = tid; i < RMAX; i += 256) h[i] = 0;
    __syncthreads();
    const int base = b * 1024;
    int rr[4];
#pragma unroll
    for (int k = 0; k < 4; ++k) {
        const int e = base + k * 256 + tid;
        rr[k] = (e < E) ? __ldg(rels + e) : -1;
        if (rr[k] >= 0) atomicAdd(&h[rr[k]], 1);
    }
    __syncthreads();
    for (int i = tid; i < RMAX; i += 256) {
        const int v = h[i];
        cur[i] = v ? atomicAdd(&g_cur[i], v) : 0;
    }
    __syncthreads();
#pragma unroll
    for (int k = 0; k < 4; ++k) {
        if (rr[k] >= 0) {
            const int e   = base + k * 256 + tid;
            const int pos = atomicAdd(&cur[rr[k]], 1);
            g_edge[pos] = make_int4(__ldg(edges + e), __ldg(edges + E + e), e, 0);
        }
    }
}

// ---- launch 3: fused attn+msg+self-loop; smem-staged edge rows; red.v4 ----------
__global__ void __launch_bounds__(256)
k_main(const float* __restrict__ node_feat,
       const float* __restrict__ ttr,   // [E,32]
       const float* __restrict__ tre,   // [E,32]
       const float* __restrict__ A_w,   // [32,128]
       const float* __restrict__ B_w,   // [32]
       const float* __restrict__ B_b,   // [1]
       float*       __restrict__ out)
{
    const int r     = blockIdx.x;
    const int start = __ldg(&g_off[r]);
    const int end   = __ldg(&g_off[r + 1]);
    if (start >= end) return;            // block-uniform

    const int tid  = threadIdx.x;
    const int lane = tid & 31;
    const int wslot = tid >> 5;          // warp within block (0..7)

    // are/atr coefficients + rel_w column pairs in smem
    __shared__ u64 sAre[32 * 17];
    __shared__ u64 sAtr[32 * 17];
    __shared__ u64 sRw [16 * 32];         // rel_w[r] packed: [i][lane]
    // per-warp staging for 4 edges x {tre,ttr,feat} rows (32 floats each)
    __shared__ float sX[8][4][32];
    __shared__ float sY[8][4][32];
    __shared__ float sF[8][4][32];

    for (int idx = tid; idx < 32 * 16; idx += 256) {
        const int row = idx >> 4, i = idx & 15;
        sAre[row * 17 + i] = pk2(__ldg(A_w + row * 128 + 64 + 2*i),
                                 __ldg(A_w + row * 128 + 64 + 2*i + 1));
        sAtr[row * 17 + i] = pk2(__ldg(A_w + row * 128 + 96 + 2*i),
                                 __ldg(A_w + row * 128 + 96 + 2*i + 1));
    }
    for (int idx = tid; idx < 512; idx += 256) {
        const int i = idx >> 5, ln = idx & 31;
        sRw[i * 32 + ln] = pk2(__ldg(&g_relw[r * 1024 + i * 64 + ln]),
                               __ldg(&g_relw[r * 1024 + i * 64 + 32 + ln]));
    }
    __syncthreads();

    const float bw = __ldg(B_w + lane);
    const float bb = __ldg(B_b);

    const int w = blockIdx.y * 8 + wslot;
    const int W = gridDim.y * 8;

    for (int i0 = start + w * 4; i0 < end; i0 += W * 4) {
        int ss[4], tt[4], ee[4];
#pragma unroll
        for (int k = 0; k < 4; ++k) {
            const int4 e4 = __ldg(&g_edge[min(i0 + k, end - 1)]);
            ss[k] = e4.x; tt[k] = e4.y; ee[k] = e4.z;
        }
        float hh[4], sl[4];
#pragma unroll
        for (int k = 0; k < 4; ++k) {
            const float2 hts = __ldg(&g_htsl[(size_t)tt[k] * 32 + lane]);
            hh[k] = __ldg(&g_hs[(size_t)ss[k] * 32 + lane]) + hts.x;
            sl[k] = hts.y;
        }

        // ---- coalesced staging: lane = element index, 12 wavefronts total ----
        __syncwarp();    // previous iteration's smem reads complete
#pragma unroll
        for (int k = 0; k < 4; ++k) {
            sX[wslot][k][lane] = __ldg(tre + (size_t)ee[k] * 32 + lane);
            sY[wslot][k][lane] = __ldg(ttr + (size_t)ee[k] * 32 + lane);
            sF[wslot][k][lane] = __ldg(node_feat + (size_t)ss[k] * 32 + lane);
        }
        __syncwarp();

        // ---- phase 1: attention (broadcast LDS reads) ----
        float p[4];
        {
            u64 aacc[4] = {0ull, 0ull, 0ull, 0ull};
#pragma unroll
            for (int c = 0; c < 8; ++c) {
                const u64 a0 = sAre[lane * 17 + 2*c];
                const u64 a1 = sAre[lane * 17 + 2*c + 1];
                const u64 t0 = sAtr[lane * 17 + 2*c];
                const u64 t1 = sAtr[lane * 17 + 2*c + 1];
#pragma unroll
                for (int k = 0; k < 4; ++k) {
                    const ulonglong2 X = *((const ulonglong2*)&sX[wslot][k][0] + c);
                    const ulonglong2 Y = *((const ulonglong2*)&sY[wslot][k][0] + c);
                    fma2(aacc[k], X.x, a0);  fma2(aacc[k], X.y, a1);
                    fma2(aacc[k], Y.x, t0);  fma2(aacc[k], Y.y, t1);
                }
            }
#pragma unroll
            for (int k = 0; k < 4; ++k)
                p[k] = fmaxf(hh[k] + upk_sum(aacc[k]), 0.f) * bw;
        }
#pragma unroll
        for (int o = 16; o; o >>= 1) {
#pragma unroll
            for (int k = 0; k < 4; ++k)
                p[k] += __shfl_xor_sync(0xffffffffu, p[k], o);
        }
        float att[4];
#pragma unroll
        for (int k = 0; k < 4; ++k)
            att[k] = 1.f / (1.f + __expf(-(p[k] + bb)));

        // ---- phase 2: message ----
        float v[4];
        {
            u64 macc[4] = {0ull, 0ull, 0ull, 0ull};
#pragma unroll
            for (int c = 0; c < 8; ++c) {
                const u64 r0 = sRw[(2*c)     * 32 + lane];
                const u64 r1 = sRw[(2*c + 1) * 32 + lane];
#pragma unroll
                for (int k = 0; k < 4; ++k) {
                    const ulonglong2 F = *((const ulonglong2*)&sF[wslot][k][0] + c);
                    fma2(macc[k], F.x, r0);
                    fma2(macc[k], F.y, r1);
                }
            }
#pragma unroll
            for (int k = 0; k < 4; ++k)
                v[k] = fmaf(upk_sum(macc[k]), att[k], sl[k]);
        }

        // all 32 lanes issue one red.v4: lane group k = edge k, 8 lanes each
        const int kk = lane >> 3;           // which edge this lane stores
        const int g0 = (lane & 7) * 4;      // feature offset
        float q0 = 0.f, q1 = 0.f, q2 = 0.f, q3 = 0.f;
#pragma unroll
        for (int k = 0; k < 4; ++k) {
            float a  = __shfl_sync(0xffffffffu, v[k], g0 + 0);
            float bq = __shfl_sync(0xffffffffu, v[k], g0 + 1);
            float cq = __shfl_sync(0xffffffffu, v[k], g0 + 2);
            float dq = __shfl_sync(0xffffffffu, v[k], g0 + 3);
            if (kk == k) { q0 = a; q1 = bq; q2 = cq; q3 = dq; }
        }
        if (i0 + kk < end) {
            float* p_ = out + (size_t)tt[kk] * 32 + g0;
            asm volatile("red.global.add.v4.f32 [%0], {%1, %2, %3, %4};"
                         :: "l"(p_), "f"(q0), "f"(q1), "f"(q2), "f"(q3) : "memory");
        }
    }
}

extern "C" void kernel_launch(void* const* d_in, const int* in_sizes, int n_in,
                              void* d_out, int out_size)
{
    const float* node_feat = (const float*)d_in[0];
    const float* ttr       = (const float*)d_in[1];
    const float* tre       = (const float*)d_in[2];
    const float* weight    = (const float*)d_in[3];
    const float* w_comp    = (const float*)d_in[4];
    const float* slw       = (const float*)d_in[5];
    const float* A_w       = (const float*)d_in[6];
    const float* A_b       = (const float*)d_in[7];
    const float* B_w       = (const float*)d_in[8];
    const float* B_b       = (const float*)d_in[9];
    const int*   edges     = (const int*)d_in[10];
    const int*   rels      = (const int*)d_in[11];
    float* out = (float*)d_out;

    const int E  = in_sizes[11];
    const int N  = in_sizes[0] / 32;
    const int NB = in_sizes[3] / 1024;
    const int R  = in_sizes[4] / NB;

    const int nbNode = (N + 63) / 64;
    const int nbHist = (E + 2047) / 2048;
    const int nbScat = (E + 1023) / 1024;
    const int nbZero = (out_size + 1023) / 1024;   // 256 thr * 4 floats

    void* cptr = nullptr;
    cudaGetSymbolAddress(&cptr, g_c);
    cudaMemsetAsync(cptr, 0, sizeof(Counters));

    k_pre<<<R + nbNode + nbHist, 256>>>(weight, w_comp, node_feat, A_w, A_b,
                                        slw, rels, NB, R, N, E, nbNode, nbHist);
    k_scat<<<nbScat + nbZero, 256>>>(edges, rels, out, E, nbScat, out_size);
    k_main<<<dim3(R, 6), 256>>>(node_feat, ttr, tre, A_w, B_w, B_b, out);
}